// round 14
// baseline (speedup 1.0000x reference)
#include <cuda_runtime.h>
#include <cuda_fp16.h>
#include <cstdint>
#include <math.h>

#define BB 4
#define NQ 4096
#define NKV 4096
#define CC 128
#define FF 128
#define BN 128
#define NT (NKV / BN)
#define REG 16384            // projection kernels: 64-col half-region
#define TPADB 272            // flash: padded row pitch (bytes), conflict-free ldmatrix
#define TILE_B (128 * TPADB) // 34816 B per staged tile
#define OPITCH 132           // epilogue smem float pitch

// fp16 operands (device globals: allocation-free rule)
__device__ __half g_Q[BB * NQ * FF];    // [b,n,f] pre-scaled by log2e/sqrt(128)
__device__ __half g_K[BB * NKV * FF];   // [b,m,f]
__device__ __half g_VT[BB * FF * NKV];  // [b,f,m]
__device__ __half g_WT[3 * CC * FF];    // Wq^T, Wk^T, Wv^T fp16 [f][c]

// ---------------------------------------------------------------------------
__device__ __forceinline__ uint32_t smem_u32(const void* p) {
  uint32_t a;
  asm("{ .reg .u64 t; cvta.to.shared.u64 t, %1; cvt.u32.u64 %0, t; }" : "=r"(a) : "l"(p));
  return a;
}
__device__ __forceinline__ uint32_t swz(uint32_t r, uint32_t cb) {
  return r * 128u + (cb ^ ((r & 7u) << 4));
}
__device__ __forceinline__ float ex2f(float x) {
  float y;
  asm("ex2.approx.f32 %0, %1;" : "=f"(y) : "f"(x));
  return y;
}

#define LDSM_X4(bb, addr)                                                      \
  asm volatile("ldmatrix.sync.aligned.m8n8.x4.shared.b16 {%0,%1,%2,%3}, [%4];" \
               : "=r"((bb)[0]), "=r"((bb)[1]), "=r"((bb)[2]), "=r"((bb)[3])    \
               : "r"(addr))

__device__ __forceinline__ void mma16816(float c[4], const uint32_t a[4],
                                         const uint32_t b[2]) {
  asm volatile(
      "mma.sync.aligned.m16n8k16.row.col.f32.f16.f16.f32 "
      "{%0,%1,%2,%3}, {%4,%5,%6,%7}, {%8,%9}, {%0,%1,%2,%3};"
      : "+f"(c[0]), "+f"(c[1]), "+f"(c[2]), "+f"(c[3])
      : "r"(a[0]), "r"(a[1]), "r"(a[2]), "r"(a[3]), "r"(b[0]), "r"(b[1]));
}

#define CP_COMMIT() asm volatile("cp.async.commit_group;" ::: "memory")
#define CP_WAIT1() asm volatile("cp.async.wait_group 1;" ::: "memory")
#define CP_WAIT0() asm volatile("cp.async.wait_group 0;" ::: "memory")
#define CP16(dst, src) \
  asm volatile("cp.async.ca.shared.global [%0], [%1], 16;" ::"r"(dst), "l"(src) : "memory")

// flash staging: 128x128 fp16 tile into TPADB-padded smem (256 threads)
__device__ __forceinline__ void stage_async(const __half* __restrict__ g,
                                            size_t gstride, char* s, int t) {
  uint32_t sb = smem_u32(s);
#pragma unroll
  for (int i = 0; i < 8; ++i) {
    int idx = t + i * 256;
    int r = idx >> 4, c = idx & 15;
    uint32_t dst = sb + r * TPADB + c * 16;
    CP16(dst, (const void*)(g + (size_t)r * gstride + c * 8));
  }
}

// projection staging: 128x128 fp16 tile into 2 swizzled 16KB regions
__device__ __forceinline__ void stage_tile256(const __half* __restrict__ g,
                                              size_t gstride, uint32_t sb, int t) {
#pragma unroll
  for (int i = 0; i < 8; ++i) {
    int idx = t + i * 256;
    uint32_t r = idx >> 4, c = idx & 15;
    uint32_t dst = sb + (c >> 3) * REG + swz(r, (c & 7) * 16);
    CP16(dst, (const void*)(g + (size_t)r * gstride + c * 8));
  }
}

// ===========================================================================
// prep: W fp32 [c][f] -> WT fp16 [f][c].  48 blocks: (matrix, f-stripe of 8).
// Stores coalesced; scattered reads are tiny and L2-parallel.
// ===========================================================================
__global__ __launch_bounds__(256) void prep_wt(const float* __restrict__ Wq,
                                               const float* __restrict__ Wk,
                                               const float* __restrict__ Wv,
                                               __half* __restrict__ WT) {
  const int m = blockIdx.x >> 4, stripe = blockIdx.x & 15;
  const float* W = m == 0 ? Wq : (m == 1 ? Wk : Wv);
  __half* O = WT + m * (CC * FF);
  const int t = threadIdx.x;
#pragma unroll
  for (int i = 0; i < 4; ++i) {
    int idx = t + i * 256;             // 0..1023 over 8 f x 128 c
    int f = stripe * 8 + (idx >> 7), c = idx & 127;
    O[f * CC + c] = __float2half(W[c * FF + f]);
  }
}

// ---------------------------------------------------------------------------
__device__ __forceinline__ void stage_x_fp16(const float* __restrict__ X,
                                             size_t R0, char* sX, int t) {
#pragma unroll
  for (int i = 0; i < 16; ++i) {
    int idx = t + i * 256;
    uint32_t r = idx >> 5, cq = idx & 31;
    float4 v = *(const float4*)(X + (R0 + r) * CC + cq * 4);
    __half2 h0 = __floats2half2_rn(v.x, v.y);
    __half2 h1 = __floats2half2_rn(v.z, v.w);
    uint32_t fb = cq * 8;
    uint32_t off = (fb >> 7) * REG + swz(r, fb & 127);
    *(uint2*)(sX + off) = make_uint2(*(uint32_t*)&h0, *(uint32_t*)&h1);
  }
}

__device__ __forceinline__ void load_afrags(uint32_t Af[8][4], uint32_t base,
                                            int bd, int lane) {
  uint32_t ar = bd * 16 + (lane & 15);
#pragma unroll
  for (int k = 0; k < 8; ++k) {
    uint32_t fb = k * 32 + (lane >> 4) * 16;
    LDSM_X4(Af[k], base + (fb >> 7) * REG + swz(ar, fb & 127));
  }
}

__device__ __forceinline__ void gemm_16x64(float c[8][4], const uint32_t Af[8][4],
                                           uint32_t bbase, int nh, int lane) {
  uint32_t br = nh * 64 + (lane & 7);
  uint32_t cb8 = ((lane >> 3) & 3) * 16;
#pragma unroll
  for (int jq = 0; jq < 2; ++jq)
#pragma unroll
    for (int p = 0; p < 4; ++p)
#pragma unroll
      for (int jj = 0; jj < 4; ++jj) {
        int j = jq * 4 + jj;
        uint32_t r = br + j * 8;
        uint32_t fb = p * 64 + cb8;
        uint32_t bb[4];
        LDSM_X4(bb, bbase + (fb >> 7) * REG + swz(r, fb & 127));
        mma16816(c[j], Af[2 * p], bb);
        mma16816(c[j], Af[2 * p + 1], bb + 2);
      }
}

// ===========================================================================
// proj_q: Y[r][f] = (X@W + b) * scale, fp16 row-major out.
// ===========================================================================
__global__ __launch_bounds__(256) void proj_q(const float* __restrict__ X,
                                              const __half* __restrict__ WT,
                                              const float* __restrict__ bias,
                                              __half* __restrict__ Y, float scale) {
  extern __shared__ char sm[];
  char* sX = sm;
  char* sW = sm + 32768;
  const int t = threadIdx.x, lane = t & 31, w = t >> 5;
  const int band = w >> 1, nh = w & 1, g = lane >> 2, qd = lane & 3;
  const size_t R0 = (size_t)blockIdx.x * 128;

  stage_tile256(WT, CC, smem_u32(sW), t);
  CP_COMMIT();
  stage_x_fp16(X, R0, sX, t);
  CP_WAIT0();
  __syncthreads();

#pragma unroll
  for (int h = 0; h < 2; ++h) {
    const int bd = band + 4 * h;
    uint32_t Af[8][4];
    load_afrags(Af, smem_u32(sX), bd, lane);

    float c[8][4];
#pragma unroll
    for (int j = 0; j < 8; ++j)
#pragma unroll
      for (int i = 0; i < 4; ++i) c[j][i] = 0.f;
    gemm_16x64(c, Af, smem_u32(sW), nh, lane);

    const size_t r0 = R0 + bd * 16 + g;
#pragma unroll
    for (int j = 0; j < 8; ++j) {
      int f = nh * 64 + j * 8 + qd * 2;
      float2 bv2 = *(const float2*)(bias + f);
      __half2 h0 = __floats2half2_rn((c[j][0] + bv2.x) * scale, (c[j][1] + bv2.y) * scale);
      __half2 h1 = __floats2half2_rn((c[j][2] + bv2.x) * scale, (c[j][3] + bv2.y) * scale);
      *(uint32_t*)(Y + r0 * FF + f) = *(uint32_t*)&h0;
      *(uint32_t*)(Y + (r0 + 8) * FF + f) = *(uint32_t*)&h1;
    }
  }
}

// ===========================================================================
// proj_kv: fused K and batch-aware VT.
// ===========================================================================
__global__ __launch_bounds__(256) void proj_kv(
    const float* __restrict__ X, const __half* __restrict__ WkT,
    const __half* __restrict__ WvT, const float* __restrict__ bk,
    const float* __restrict__ bv, __half* __restrict__ K, __half* __restrict__ VT) {
  extern __shared__ char sm[];
  char* sX = sm;
  char* sWk = sm + 32768;
  char* sWv = sm + 65536;
  const int t = threadIdx.x, lane = t & 31, w = t >> 5;
  const int band = w >> 1, nh = w & 1, g = lane >> 2, qd = lane & 3;
  const size_t R0 = (size_t)blockIdx.x * 128;

  stage_tile256(WkT, CC, smem_u32(sWk), t);
  stage_tile256(WvT, CC, smem_u32(sWv), t);
  CP_COMMIT();
  stage_x_fp16(X, R0, sX, t);
  CP_WAIT0();
  __syncthreads();

#pragma unroll
  for (int h = 0; h < 2; ++h) {
    const int bd = band + 4 * h;
    uint32_t Af[8][4];
    load_afrags(Af, smem_u32(sX), bd, lane);
    float c[8][4];
#pragma unroll
    for (int j = 0; j < 8; ++j)
#pragma unroll
      for (int i = 0; i < 4; ++i) c[j][i] = 0.f;
    gemm_16x64(c, Af, smem_u32(sWk), nh, lane);

    const size_t r0 = R0 + bd * 16 + g;
#pragma unroll
    for (int j = 0; j < 8; ++j) {
      int f = nh * 64 + j * 8 + qd * 2;
      float2 bv2 = *(const float2*)(bk + f);
      __half2 h0 = __floats2half2_rn(c[j][0] + bv2.x, c[j][1] + bv2.y);
      __half2 h1 = __floats2half2_rn(c[j][2] + bv2.x, c[j][3] + bv2.y);
      *(uint32_t*)(K + r0 * FF + f) = *(uint32_t*)&h0;
      *(uint32_t*)(K + (r0 + 8) * FF + f) = *(uint32_t*)&h1;
    }
  }

  const int bidx = (int)(R0 >> 12);
  const size_t mbase = (R0 & 4095);
  __half* VTb = VT + (size_t)bidx * FF * NKV;
#pragma unroll
  for (int h = 0; h < 2; ++h) {
    const int bd = band + 4 * h;
    uint32_t Af[8][4];
    load_afrags(Af, smem_u32(sWv), bd, lane);
    float c[8][4];
#pragma unroll
    for (int j = 0; j < 8; ++j)
#pragma unroll
      for (int i = 0; i < 4; ++i) c[j][i] = 0.f;
    gemm_16x64(c, Af, smem_u32(sX), nh, lane);

    const int f0 = bd * 16 + g;
    const float blo = bv[f0], bhi = bv[f0 + 8];
#pragma unroll
    for (int j = 0; j < 8; ++j) {
      size_t col = mbase + nh * 64 + j * 8 + qd * 2;
      __half2 h0 = __floats2half2_rn(c[j][0] + blo, c[j][1] + blo);
      __half2 h1 = __floats2half2_rn(c[j][2] + bhi, c[j][3] + bhi);
      *(uint32_t*)(VTb + (size_t)f0 * NKV + col) = *(uint32_t*)&h0;
      *(uint32_t*)(VTb + (size_t)(f0 + 8) * NKV + col) = *(uint32_t*)&h1;
    }
  }
}

// ===========================================================================
// Flash attention v8: v6 tiling (8 warps = 4 bands x 2 kv-halves, 32q x 64kv
// warp tile) + TRIPLE-BUFFERED K/V tiles -> ONE __syncthreads per iteration.
// Buffer staged at iter j+3 was last read at iter j; the single top-sync of
// each intervening iteration transitively orders all warps' reads first.
// smem: 3*(K+V) tiles = 204 KB; epilogue reuses buffer 0 region after a sync.
// ===========================================================================
__global__ __launch_bounds__(256, 1) void flash_kernel(
    const __half* __restrict__ Qg, const __half* __restrict__ Kg,
    const __half* __restrict__ VTg, float* __restrict__ Og) {
  extern __shared__ char smem[];
  char* sK[3] = {smem, smem + TILE_B, smem + 2 * TILE_B};
  char* sV[3] = {smem + 3 * TILE_B, smem + 4 * TILE_B, smem + 5 * TILE_B};

  const int t = threadIdx.x, lane = t & 31, w = t >> 5;
  const int band = w >> 1, nh = w & 1;
  const int g = lane >> 2, qd = lane & 3;
  const int b = blockIdx.y, qt = blockIdx.x;

  // Q fragments for 32 rows (band*32 .. +31): upper 16 + lower 16
  const __half* Qw = Qg + ((size_t)(b * NQ + qt * 128 + band * 32)) * FF;
  uint32_t Qfu[8][4], Qfd[8][4];
#pragma unroll
  for (int k = 0; k < 8; ++k) {
    int c0 = k * 16 + qd * 2;
    Qfu[k][0] = *(const uint32_t*)(Qw + g * FF + c0);
    Qfu[k][1] = *(const uint32_t*)(Qw + (g + 8) * FF + c0);
    Qfu[k][2] = *(const uint32_t*)(Qw + g * FF + c0 + 8);
    Qfu[k][3] = *(const uint32_t*)(Qw + (g + 8) * FF + c0 + 8);
    Qfd[k][0] = *(const uint32_t*)(Qw + (g + 16) * FF + c0);
    Qfd[k][1] = *(const uint32_t*)(Qw + (g + 24) * FF + c0);
    Qfd[k][2] = *(const uint32_t*)(Qw + (g + 16) * FF + c0 + 8);
    Qfd[k][3] = *(const uint32_t*)(Qw + (g + 24) * FF + c0 + 8);
  }

  const __half* Kb = Kg + (size_t)b * NKV * FF;
  const __half* Vb = VTg + (size_t)b * FF * NKV;

  stage_async(Kb, FF, sK[0], t);
  stage_async(Vb, NKV, sV[0], t);
  CP_COMMIT();

  float Ou[16][4], Od[16][4];
#pragma unroll
  for (int j = 0; j < 16; ++j)
#pragma unroll
    for (int i = 0; i < 4; ++i) { Ou[j][i] = 0.f; Od[j][i] = 0.f; }
  float s0 = 0.f, s1 = 0.f, s2 = 0.f, s3 = 0.f;  // rows g, g+8, g+16, g+24

  const uint32_t lmoff = (uint32_t)(lane & 7) * TPADB + (uint32_t)(lane >> 3) * 16;
  const uint32_t khalf = (uint32_t)nh * 64 * TPADB;
  const uint32_t vcol = (uint32_t)nh * 128;

  int cur = 0, nxt = 1;
#pragma unroll 1
  for (int jt = 0; jt < NT; ++jt) {
    if (jt + 1 < NT) {
      stage_async(Kb + (size_t)(jt + 1) * BN * FF, FF, sK[nxt], t);
      stage_async(Vb + (size_t)(jt + 1) * BN, NKV, sV[nxt], t);
      CP_COMMIT();
      CP_WAIT1();
    } else {
      CP_WAIT0();
    }
    __syncthreads();  // single barrier per iteration (triple buffering)

    const uint32_t kbase = smem_u32(sK[cur]) + khalf + lmoff;
    const uint32_t vbase = smem_u32(sV[cur]) + lmoff + vcol;

#pragma unroll
    for (int jq = 0; jq < 2; ++jq) {
      const uint32_t ka = kbase + (uint32_t)jq * 4 * (8 * TPADB);

      // ---- S slice: 32 rows x 32 kv, k=128; LDSM pipelined 1 ahead ----
      float cu[4][4], cd[4][4];
#pragma unroll
      for (int jj = 0; jj < 4; ++jj)
#pragma unroll
        for (int i = 0; i < 4; ++i) { cu[jj][i] = 0.f; cd[jj][i] = 0.f; }

      uint32_t kb[2][4];
      LDSM_X4(kb[0], ka);
#pragma unroll
      for (int i = 0; i < 16; ++i) {
        if (i < 15) {
          int ni = i + 1;
          LDSM_X4(kb[(i + 1) & 1],
                  ka + (uint32_t)(ni & 3) * (8 * TPADB) + (ni >> 2) * 64);
        }
        const int p = i >> 2, jj = i & 3;
        mma16816(cu[jj], Qfu[2 * p], kb[i & 1]);
        mma16816(cu[jj], Qfu[2 * p + 1], kb[i & 1] + 2);
        mma16816(cd[jj], Qfd[2 * p], kb[i & 1]);
        mma16816(cd[jj], Qfd[2 * p + 1], kb[i & 1] + 2);
      }

      // prefetch first V fragment of PV loop before the exp block
      uint32_t vb[2][4];
      LDSM_X4(vb[0], vbase + jq * 64);

      // ---- exp2 + pack ----
      uint32_t Pfu[2][4], Pfd[2][4];
#pragma unroll
      for (int jj = 0; jj < 4; ++jj) {
        int kk = jj >> 1, o = (jj & 1) * 2;
        float e0 = ex2f(cu[jj][0]), e1 = ex2f(cu[jj][1]);
        float e2 = ex2f(cu[jj][2]), e3 = ex2f(cu[jj][3]);
        s0 += e0 + e1;
        s1 += e2 + e3;
        __half2 hu01 = __floats2half2_rn(e0, e1);
        __half2 hu23 = __floats2half2_rn(e2, e3);
        Pfu[kk][o] = *(uint32_t*)&hu01;
        Pfu[kk][o + 1] = *(uint32_t*)&hu23;
        float f0 = ex2f(cd[jj][0]), f1 = ex2f(cd[jj][1]);
        float f2 = ex2f(cd[jj][2]), f3 = ex2f(cd[jj][3]);
        s2 += f0 + f1;
        s3 += f2 + f3;
        __half2 hd01 = __floats2half2_rn(f0, f1);
        __half2 hd23 = __floats2half2_rn(f2, f3);
        Pfd[kk][o] = *(uint32_t*)&hd01;
        Pfd[kk][o + 1] = *(uint32_t*)&hd23;
      }

      // ---- PV slice: k = 32 kv, all 128 features; LDSM pipelined 1 ahead ----
#pragma unroll
      for (int j = 0; j < 16; ++j) {
        if (j < 15) {
          LDSM_X4(vb[(j + 1) & 1],
                  vbase + (uint32_t)(j + 1) * (8 * TPADB) + jq * 64);
        }
        mma16816(Ou[j], Pfu[0], vb[j & 1]);
        mma16816(Ou[j], Pfu[1], vb[j & 1] + 2);
        mma16816(Od[j], Pfd[0], vb[j & 1]);
        mma16816(Od[j], Pfd[1], vb[j & 1] + 2);
      }
    }

    cur = cur == 2 ? 0 : cur + 1;
    nxt = nxt == 2 ? 0 : nxt + 1;
  }
  __syncthreads();  // all reads done before epilogue reuses buffer region

  // ---- reduce row sums within quads ----
  s0 += __shfl_xor_sync(0xffffffffu, s0, 1);
  s0 += __shfl_xor_sync(0xffffffffu, s0, 2);
  s1 += __shfl_xor_sync(0xffffffffu, s1, 1);
  s1 += __shfl_xor_sync(0xffffffffu, s1, 2);
  s2 += __shfl_xor_sync(0xffffffffu, s2, 1);
  s2 += __shfl_xor_sync(0xffffffffu, s2, 2);
  s3 += __shfl_xor_sync(0xffffffffu, s3, 1);
  s3 += __shfl_xor_sync(0xffffffffu, s3, 2);

  // ---- combine kv-halves: nh1 dumps O + l to smem, nh0 adds + writes ----
  float* sO = (float*)smem;                          // 4 bands x 32 rows x OPITCH
  float* sL = (float*)(smem + 4 * 32 * OPITCH * 4);  // 4 bands x 32 rows
  if (nh == 1) {
    float* dst = sO + band * 32 * OPITCH;
#pragma unroll
    for (int j = 0; j < 16; ++j) {
      int f = j * 8 + qd * 2;
      *(float2*)(dst + g * OPITCH + f) = make_float2(Ou[j][0], Ou[j][1]);
      *(float2*)(dst + (g + 8) * OPITCH + f) = make_float2(Ou[j][2], Ou[j][3]);
      *(float2*)(dst + (g + 16) * OPITCH + f) = make_float2(Od[j][0], Od[j][1]);
      *(float2*)(dst + (g + 24) * OPITCH + f) = make_float2(Od[j][2], Od[j][3]);
    }
    if (qd == 0) {
      float* lb = sL + band * 32;
      lb[g] = s0;
      lb[g + 8] = s1;
      lb[g + 16] = s2;
      lb[g + 24] = s3;
    }
  }
  __syncthreads();
  if (nh == 0) {
    const float* src = sO + band * 32 * OPITCH;
    const float* lb = sL + band * 32;
    const float r0 = 1.0f / (s0 + lb[g]);
    const float r1 = 1.0f / (s1 + lb[g + 8]);
    const float r2 = 1.0f / (s2 + lb[g + 16]);
    const float r3 = 1.0f / (s3 + lb[g + 24]);
    float* Ob = Og + ((size_t)(b * NQ + qt * 128 + band * 32)) * FF;
#pragma unroll
    for (int j = 0; j < 16; ++j) {
      int f = j * 8 + qd * 2;
      float2 a0 = *(const float2*)(src + g * OPITCH + f);
      float2 a1 = *(const float2*)(src + (g + 8) * OPITCH + f);
      float2 a2 = *(const float2*)(src + (g + 16) * OPITCH + f);
      float2 a3 = *(const float2*)(src + (g + 24) * OPITCH + f);
      *(float2*)(Ob + (size_t)g * FF + f) =
          make_float2((Ou[j][0] + a0.x) * r0, (Ou[j][1] + a0.y) * r0);
      *(float2*)(Ob + (size_t)(g + 8) * FF + f) =
          make_float2((Ou[j][2] + a1.x) * r1, (Ou[j][3] + a1.y) * r1);
      *(float2*)(Ob + (size_t)(g + 16) * FF + f) =
          make_float2((Od[j][0] + a2.x) * r2, (Od[j][1] + a2.y) * r2);
      *(float2*)(Ob + (size_t)(g + 24) * FF + f) =
          make_float2((Od[j][2] + a3.x) * r3, (Od[j][3] + a3.y) * r3);
    }
  }
}

// ===========================================================================
extern "C" void kernel_launch(void* const* d_in, const int* in_sizes, int n_in,
                              void* d_out, int out_size) {
  const float* qin  = (const float*)d_in[0];
  const float* kvin = (const float*)d_in[1];
  const float* Wq   = (const float*)d_in[2];
  const float* bq   = (const float*)d_in[3];
  const float* Wk   = (const float*)d_in[4];
  const float* bk   = (const float*)d_in[5];
  const float* Wv   = (const float*)d_in[6];
  const float* bv   = (const float*)d_in[7];
  float* out = (float*)d_out;

  __half *dQ, *dK, *dVT, *dWT;
  cudaGetSymbolAddress((void**)&dQ, g_Q);
  cudaGetSymbolAddress((void**)&dK, g_K);
  cudaGetSymbolAddress((void**)&dVT, g_VT);
  cudaGetSymbolAddress((void**)&dWT, g_WT);

  const int smq = 2 * 32768;
  const int smkv = 3 * 32768;
  const int smf = 6 * TILE_B;  // 208896 (triple-buffered K+V)
  cudaFuncSetAttribute(proj_q, cudaFuncAttributeMaxDynamicSharedMemorySize, smq);
  cudaFuncSetAttribute(proj_kv, cudaFuncAttributeMaxDynamicSharedMemorySize, smkv);
  cudaFuncSetAttribute(flash_kernel, cudaFuncAttributeMaxDynamicSharedMemorySize, smf);

  prep_wt<<<48, 256>>>(Wq, Wk, Wv, dWT);

  // Q pre-scale: log2(e)/sqrt(128); flash uses exp2
  const float qscale = 0.127518749639422f;
  proj_q<<<BB * NQ / 128, 256, smq>>>(qin, dWT, bq, dQ, qscale);
  proj_kv<<<BB * NKV / 128, 256, smkv>>>(kvin, dWT + CC * FF, dWT + 2 * CC * FF,
                                         bk, bv, dK, dVT);

  dim3 fg(NQ / 128, BB);
  flash_kernel<<<fg, 256, smf>>>(dQ, dK, dVT, out);
}

// round 15
// speedup vs baseline: 1.0977x; 1.0977x over previous
#include <cuda_runtime.h>
#include <cuda_fp16.h>
#include <cstdint>
#include <math.h>

#define BB 4
#define NQ 4096
#define NKV 4096
#define CC 128
#define FF 128
#define BN 128
#define NT (NKV / BN)
#define REG 16384            // projection kernels: 64-col half-region
#define TPADB 272            // flash: padded row pitch (bytes), conflict-free ldmatrix
#define TILE_B (128 * TPADB) // 34816 B per staged tile
#define OPITCH 132           // epilogue smem float pitch

// fp16 operands (device globals: allocation-free rule)
__device__ __half g_Q[BB * NQ * FF];    // [b,n,f] pre-scaled by log2e/sqrt(128)
__device__ __half g_K[BB * NKV * FF];   // [b,m,f]
__device__ __half g_VT[BB * FF * NKV];  // [b,f,m]
__device__ __half g_WT[3 * CC * FF];    // Wq^T, Wk^T, Wv^T fp16 [f][c]

// ---------------------------------------------------------------------------
__device__ __forceinline__ uint32_t smem_u32(const void* p) {
  uint32_t a;
  asm("{ .reg .u64 t; cvta.to.shared.u64 t, %1; cvt.u32.u64 %0, t; }" : "=r"(a) : "l"(p));
  return a;
}
__device__ __forceinline__ uint32_t swz(uint32_t r, uint32_t cb) {
  return r * 128u + (cb ^ ((r & 7u) << 4));
}
__device__ __forceinline__ float ex2f(float x) {
  float y;
  asm("ex2.approx.f32 %0, %1;" : "=f"(y) : "f"(x));
  return y;
}

#define LDSM_X4(bb, addr)                                                      \
  asm volatile("ldmatrix.sync.aligned.m8n8.x4.shared.b16 {%0,%1,%2,%3}, [%4];" \
               : "=r"((bb)[0]), "=r"((bb)[1]), "=r"((bb)[2]), "=r"((bb)[3])    \
               : "r"(addr))

__device__ __forceinline__ void mma16816(float c[4], const uint32_t a[4],
                                         const uint32_t b[2]) {
  asm volatile(
      "mma.sync.aligned.m16n8k16.row.col.f32.f16.f16.f32 "
      "{%0,%1,%2,%3}, {%4,%5,%6,%7}, {%8,%9}, {%0,%1,%2,%3};"
      : "+f"(c[0]), "+f"(c[1]), "+f"(c[2]), "+f"(c[3])
      : "r"(a[0]), "r"(a[1]), "r"(a[2]), "r"(a[3]), "r"(b[0]), "r"(b[1]));
}

#define CP_COMMIT() asm volatile("cp.async.commit_group;" ::: "memory")
#define CP_WAIT1() asm volatile("cp.async.wait_group 1;" ::: "memory")
#define CP_WAIT0() asm volatile("cp.async.wait_group 0;" ::: "memory")
#define CP16(dst, src) \
  asm volatile("cp.async.ca.shared.global [%0], [%1], 16;" ::"r"(dst), "l"(src) : "memory")

// ---------------------------------------------------------------------------
// flash staging: 128x128 fp16 tile into TPADB-padded smem (256 threads)
// ---------------------------------------------------------------------------
__device__ __forceinline__ void stage_async(const __half* __restrict__ g,
                                            size_t gstride, char* s, int t) {
  uint32_t sb = smem_u32(s);
#pragma unroll
  for (int i = 0; i < 8; ++i) {
    int idx = t + i * 256;
    int r = idx >> 4, c = idx & 15;
    uint32_t dst = sb + r * TPADB + c * 16;
    CP16(dst, (const void*)(g + (size_t)r * gstride + c * 8));
  }
}

// projection staging: 128x128 fp16 tile into 2 swizzled 16KB regions
template <int NTH>
__device__ __forceinline__ void stage_tile_swz(const __half* __restrict__ g,
                                               size_t gstride, uint32_t sb, int t) {
#pragma unroll
  for (int i = 0; i < 2048 / NTH; ++i) {
    int idx = t + i * NTH;
    uint32_t r = idx >> 4, c = idx & 15;
    uint32_t dst = sb + (c >> 3) * REG + swz(r, (c & 7) * 16);
    CP16(dst, (const void*)(g + (size_t)r * gstride + c * 8));
  }
}

// ===========================================================================
// prep: W fp32 [c][f] -> WT fp16 [f][c].  48 blocks: (matrix, f-stripe of 8).
// ===========================================================================
__global__ __launch_bounds__(256) void prep_wt(const float* __restrict__ Wq,
                                               const float* __restrict__ Wk,
                                               const float* __restrict__ Wv,
                                               __half* __restrict__ WT) {
  const int m = blockIdx.x >> 4, stripe = blockIdx.x & 15;
  const float* W = m == 0 ? Wq : (m == 1 ? Wk : Wv);
  __half* O = WT + m * (CC * FF);
  const int t = threadIdx.x;
#pragma unroll
  for (int i = 0; i < 4; ++i) {
    int idx = t + i * 256;             // 0..1023 over 8 f x 128 c
    int f = stripe * 8 + (idx >> 7), c = idx & 127;
    O[f * CC + c] = __float2half(W[c * FF + f]);
  }
}

// ---------------------------------------------------------------------------
template <int NTH>
__device__ __forceinline__ void stage_x_fp16(const float* __restrict__ X,
                                             char* sX, int t) {
#pragma unroll
  for (int i = 0; i < 4096 / NTH; ++i) {
    int idx = t + i * NTH;
    uint32_t r = idx >> 5, cq = idx & 31;
    float4 v = *(const float4*)(X + (size_t)r * CC + cq * 4);
    __half2 h0 = __floats2half2_rn(v.x, v.y);
    __half2 h1 = __floats2half2_rn(v.z, v.w);
    uint32_t fb = cq * 8;
    uint32_t off = (fb >> 7) * REG + swz(r, fb & 127);
    *(uint2*)(sX + off) = make_uint2(*(uint32_t*)&h0, *(uint32_t*)&h1);
  }
}

__device__ __forceinline__ void load_afrags(uint32_t Af[8][4], uint32_t base,
                                            int bd, int lane) {
  uint32_t ar = bd * 16 + (lane & 15);
#pragma unroll
  for (int k = 0; k < 8; ++k) {
    uint32_t fb = k * 32 + (lane >> 4) * 16;
    LDSM_X4(Af[k], base + (fb >> 7) * REG + swz(ar, fb & 127));
  }
}

__device__ __forceinline__ void gemm_16x64(float c[8][4], const uint32_t Af[8][4],
                                           uint32_t bbase, int nh, int lane) {
  uint32_t br = nh * 64 + (lane & 7);
  uint32_t cb8 = ((lane >> 3) & 3) * 16;
#pragma unroll
  for (int jq = 0; jq < 2; ++jq)
#pragma unroll
    for (int p = 0; p < 4; ++p)
#pragma unroll
      for (int jj = 0; jj < 4; ++jj) {
        int j = jq * 4 + jj;
        uint32_t r = br + j * 8;
        uint32_t fb = p * 64 + cb8;
        uint32_t bb[4];
        LDSM_X4(bb, bbase + (fb >> 7) * REG + swz(r, fb & 127));
        mma16816(c[j], Af[2 * p], bb);
        mma16816(c[j], Af[2 * p + 1], bb + 2);
      }
}

// ===========================================================================
// proj_q: Y[r][f] = (X@W + b) * scale, fp16 row-major out. (256 thr, 8 warps,
// two bands per warp)
// ===========================================================================
__global__ __launch_bounds__(256) void proj_q(const float* __restrict__ X,
                                              const __half* __restrict__ WT,
                                              const float* __restrict__ bias,
                                              __half* __restrict__ Y, float scale) {
  extern __shared__ char sm[];
  char* sX = sm;
  char* sW = sm + 32768;
  const int t = threadIdx.x, lane = t & 31, w = t >> 5;
  const int band = w >> 1, nh = w & 1, g = lane >> 2, qd = lane & 3;
  const size_t R0 = (size_t)blockIdx.x * 128;

  stage_tile_swz<256>(WT, CC, smem_u32(sW), t);
  CP_COMMIT();
  stage_x_fp16<256>(X + R0 * CC, sX, t);
  CP_WAIT0();
  __syncthreads();

#pragma unroll
  for (int h = 0; h < 2; ++h) {
    const int bd = band + 4 * h;
    uint32_t Af[8][4];
    load_afrags(Af, smem_u32(sX), bd, lane);

    float c[8][4];
#pragma unroll
    for (int j = 0; j < 8; ++j)
#pragma unroll
      for (int i = 0; i < 4; ++i) c[j][i] = 0.f;
    gemm_16x64(c, Af, smem_u32(sW), nh, lane);

    const size_t r0 = R0 + bd * 16 + g;
#pragma unroll
    for (int j = 0; j < 8; ++j) {
      int f = nh * 64 + j * 8 + qd * 2;
      float2 bv2 = *(const float2*)(bias + f);
      __half2 h0 = __floats2half2_rn((c[j][0] + bv2.x) * scale, (c[j][1] + bv2.y) * scale);
      __half2 h1 = __floats2half2_rn((c[j][2] + bv2.x) * scale, (c[j][3] + bv2.y) * scale);
      *(uint32_t*)(Y + r0 * FF + f) = *(uint32_t*)&h0;
      *(uint32_t*)(Y + (r0 + 8) * FF + f) = *(uint32_t*)&h1;
    }
  }
}

// ===========================================================================
// proj_kv: fused K = X@Wk + bk and batch-aware VT. 512 threads / 16 warps:
// warp = (band = w>>1 in 0..7, nh = w&1).
// ===========================================================================
__global__ __launch_bounds__(512) void proj_kv(
    const float* __restrict__ X, const __half* __restrict__ WkT,
    const __half* __restrict__ WvT, const float* __restrict__ bk,
    const float* __restrict__ bv, __half* __restrict__ K, __half* __restrict__ VT) {
  extern __shared__ char sm[];
  char* sX = sm;
  char* sWk = sm + 32768;
  char* sWv = sm + 65536;
  const int t = threadIdx.x, lane = t & 31, w = t >> 5;
  const int band = w >> 1, nh = w & 1, g = lane >> 2, qd = lane & 3;
  const size_t R0 = (size_t)blockIdx.x * 128;

  stage_tile_swz<512>(WkT, CC, smem_u32(sWk), t);
  stage_tile_swz<512>(WvT, CC, smem_u32(sWv), t);
  CP_COMMIT();
  stage_x_fp16<512>(X + R0 * CC, sX, t);
  CP_WAIT0();
  __syncthreads();

  // ---- K projection ----
  {
    uint32_t Af[8][4];
    load_afrags(Af, smem_u32(sX), band, lane);
    float c[8][4];
#pragma unroll
    for (int j = 0; j < 8; ++j)
#pragma unroll
      for (int i = 0; i < 4; ++i) c[j][i] = 0.f;
    gemm_16x64(c, Af, smem_u32(sWk), nh, lane);

    const size_t r0 = R0 + band * 16 + g;
#pragma unroll
    for (int j = 0; j < 8; ++j) {
      int f = nh * 64 + j * 8 + qd * 2;
      float2 bv2 = *(const float2*)(bk + f);
      __half2 h0 = __floats2half2_rn(c[j][0] + bv2.x, c[j][1] + bv2.y);
      __half2 h1 = __floats2half2_rn(c[j][2] + bv2.x, c[j][3] + bv2.y);
      *(uint32_t*)(K + r0 * FF + f) = *(uint32_t*)&h0;
      *(uint32_t*)(K + (r0 + 8) * FF + f) = *(uint32_t*)&h1;
    }
  }

  // ---- VT projection (batch-aware) ----
  const int bidx = (int)(R0 >> 12);
  const size_t mbase = (R0 & 4095);
  __half* VTb = VT + (size_t)bidx * FF * NKV;
  {
    uint32_t Af[8][4];
    load_afrags(Af, smem_u32(sWv), band, lane);
    float c[8][4];
#pragma unroll
    for (int j = 0; j < 8; ++j)
#pragma unroll
      for (int i = 0; i < 4; ++i) c[j][i] = 0.f;
    gemm_16x64(c, Af, smem_u32(sX), nh, lane);

    const int f0 = band * 16 + g;
    const float blo = bv[f0], bhi = bv[f0 + 8];
#pragma unroll
    for (int j = 0; j < 8; ++j) {
      size_t col = mbase + nh * 64 + j * 8 + qd * 2;
      __half2 h0 = __floats2half2_rn(c[j][0] + blo, c[j][1] + blo);
      __half2 h1 = __floats2half2_rn(c[j][2] + bhi, c[j][3] + bhi);
      *(uint32_t*)(VTb + (size_t)f0 * NKV + col) = *(uint32_t*)&h0;
      *(uint32_t*)(VTb + (size_t)(f0 + 8) * NKV + col) = *(uint32_t*)&h1;
    }
  }
}

// ===========================================================================
// Flash attention (R12/v6, best measured): 256 threads = 8 warps = 4 bands x
// 2 kv-halves, 32q x 64kv warp tile, double-buffered tiles, pipelined LDSM.
// ===========================================================================
__global__ __launch_bounds__(256, 1) void flash_kernel(
    const __half* __restrict__ Qg, const __half* __restrict__ Kg,
    const __half* __restrict__ VTg, float* __restrict__ Og) {
  extern __shared__ char smem[];
  char* sK[2] = {smem, smem + TILE_B};
  char* sV[2] = {smem + 2 * TILE_B, smem + 3 * TILE_B};

  const int t = threadIdx.x, lane = t & 31, w = t >> 5;
  const int band = w >> 1, nh = w & 1;
  const int g = lane >> 2, qd = lane & 3;
  const int b = blockIdx.y, qt = blockIdx.x;

  // Q fragments for 32 rows (band*32 .. +31): upper 16 + lower 16
  const __half* Qw = Qg + ((size_t)(b * NQ + qt * 128 + band * 32)) * FF;
  uint32_t Qfu[8][4], Qfd[8][4];
#pragma unroll
  for (int k = 0; k < 8; ++k) {
    int c0 = k * 16 + qd * 2;
    Qfu[k][0] = *(const uint32_t*)(Qw + g * FF + c0);
    Qfu[k][1] = *(const uint32_t*)(Qw + (g + 8) * FF + c0);
    Qfu[k][2] = *(const uint32_t*)(Qw + g * FF + c0 + 8);
    Qfu[k][3] = *(const uint32_t*)(Qw + (g + 8) * FF + c0 + 8);
    Qfd[k][0] = *(const uint32_t*)(Qw + (g + 16) * FF + c0);
    Qfd[k][1] = *(const uint32_t*)(Qw + (g + 24) * FF + c0);
    Qfd[k][2] = *(const uint32_t*)(Qw + (g + 16) * FF + c0 + 8);
    Qfd[k][3] = *(const uint32_t*)(Qw + (g + 24) * FF + c0 + 8);
  }

  const __half* Kb = Kg + (size_t)b * NKV * FF;
  const __half* Vb = VTg + (size_t)b * FF * NKV;

  stage_async(Kb, FF, sK[0], t);
  stage_async(Vb, NKV, sV[0], t);
  CP_COMMIT();

  float Ou[16][4], Od[16][4];
#pragma unroll
  for (int j = 0; j < 16; ++j)
#pragma unroll
    for (int i = 0; i < 4; ++i) { Ou[j][i] = 0.f; Od[j][i] = 0.f; }
  float s0 = 0.f, s1 = 0.f, s2 = 0.f, s3 = 0.f;

  const uint32_t lmoff = (uint32_t)(lane & 7) * TPADB + (uint32_t)(lane >> 3) * 16;
  const uint32_t khalf = (uint32_t)nh * 64 * TPADB;
  const uint32_t vcol = (uint32_t)nh * 128;

#pragma unroll 1
  for (int jt = 0; jt < NT; ++jt) {
    const int cur = jt & 1;
    if (jt + 1 < NT) {
      stage_async(Kb + (size_t)(jt + 1) * BN * FF, FF, sK[cur ^ 1], t);
      stage_async(Vb + (size_t)(jt + 1) * BN, NKV, sV[cur ^ 1], t);
      CP_COMMIT();
      CP_WAIT1();
    } else {
      CP_WAIT0();
    }
    __syncthreads();

    const uint32_t kbase = smem_u32(sK[cur]) + khalf + lmoff;
    const uint32_t vbase = smem_u32(sV[cur]) + lmoff + vcol;

#pragma unroll
    for (int jq = 0; jq < 2; ++jq) {
      const uint32_t ka = kbase + (uint32_t)jq * 4 * (8 * TPADB);

      // ---- S slice: 32 rows x 32 kv, k=128; LDSM pipelined 1 ahead ----
      float cu[4][4], cd[4][4];
#pragma unroll
      for (int jj = 0; jj < 4; ++jj)
#pragma unroll
        for (int i = 0; i < 4; ++i) { cu[jj][i] = 0.f; cd[jj][i] = 0.f; }

      uint32_t kb[2][4];
      LDSM_X4(kb[0], ka);
#pragma unroll
      for (int i = 0; i < 16; ++i) {
        if (i < 15) {
          int ni = i + 1;
          LDSM_X4(kb[(i + 1) & 1],
                  ka + (uint32_t)(ni & 3) * (8 * TPADB) + (ni >> 2) * 64);
        }
        const int p = i >> 2, jj = i & 3;
        mma16816(cu[jj], Qfu[2 * p], kb[i & 1]);
        mma16816(cu[jj], Qfu[2 * p + 1], kb[i & 1] + 2);
        mma16816(cd[jj], Qfd[2 * p], kb[i & 1]);
        mma16816(cd[jj], Qfd[2 * p + 1], kb[i & 1] + 2);
      }

      // prefetch first V fragment of PV loop before the exp block
      uint32_t vb[2][4];
      LDSM_X4(vb[0], vbase + jq * 64);

      // ---- exp2 + pack ----
      uint32_t Pfu[2][4], Pfd[2][4];
#pragma unroll
      for (int jj = 0; jj < 4; ++jj) {
        int kk = jj >> 1, o = (jj & 1) * 2;
        float e0 = ex2f(cu[jj][0]), e1 = ex2f(cu[jj][1]);
        float e2 = ex2f(cu[jj][2]), e3 = ex2f(cu[jj][3]);
        s0 += e0 + e1;
        s1 += e2 + e3;
        __half2 hu01 = __floats2half2_rn(e0, e1);
        __half2 hu23 = __floats2half2_rn(e2, e3);
        Pfu[kk][o] = *(uint32_t*)&hu01;
        Pfu[kk][o + 1] = *(uint32_t*)&hu23;
        float f0 = ex2f(cd[jj][0]), f1 = ex2f(cd[jj][1]);
        float f2 = ex2f(cd[jj][2]), f3 = ex2f(cd[jj][3]);
        s2 += f0 + f1;
        s3 += f2 + f3;
        __half2 hd01 = __floats2half2_rn(f0, f1);
        __half2 hd23 = __floats2half2_rn(f2, f3);
        Pfd[kk][o] = *(uint32_t*)&hd01;
        Pfd[kk][o + 1] = *(uint32_t*)&hd23;
      }

      // ---- PV slice: k = 32 kv, all 128 features; LDSM pipelined 1 ahead ----
#pragma unroll
      for (int j = 0; j < 16; ++j) {
        if (j < 15) {
          LDSM_X4(vb[(j + 1) & 1],
                  vbase + (uint32_t)(j + 1) * (8 * TPADB) + jq * 64);
        }
        mma16816(Ou[j], Pfu[0], vb[j & 1]);
        mma16816(Ou[j], Pfu[1], vb[j & 1] + 2);
        mma16816(Od[j], Pfd[0], vb[j & 1]);
        mma16816(Od[j], Pfd[1], vb[j & 1] + 2);
      }
    }
    __syncthreads();
  }

  // ---- reduce row sums within quads ----
  s0 += __shfl_xor_sync(0xffffffffu, s0, 1);
  s0 += __shfl_xor_sync(0xffffffffu, s0, 2);
  s1 += __shfl_xor_sync(0xffffffffu, s1, 1);
  s1 += __shfl_xor_sync(0xffffffffu, s1, 2);
  s2 += __shfl_xor_sync(0xffffffffu, s2, 1);
  s2 += __shfl_xor_sync(0xffffffffu, s2, 2);
  s3 += __shfl_xor_sync(0xffffffffu, s3, 1);
  s3 += __shfl_xor_sync(0xffffffffu, s3, 2);

  // ---- combine kv-halves: nh1 dumps O + l to smem, nh0 adds + writes ----
  float* sO = (float*)smem;                          // 4 bands x 32 rows x OPITCH
  float* sL = (float*)(smem + 4 * 32 * OPITCH * 4);  // 4 bands x 32 rows
  if (nh == 1) {
    float* dst = sO + band * 32 * OPITCH;
#pragma unroll
    for (int j = 0; j < 16; ++j) {
      int f = j * 8 + qd * 2;
      *(float2*)(dst + g * OPITCH + f) = make_float2(Ou[j][0], Ou[j][1]);
      *(float2*)(dst + (g + 8) * OPITCH + f) = make_float2(Ou[j][2], Ou[j][3]);
      *(float2*)(dst + (g + 16) * OPITCH + f) = make_float2(Od[j][0], Od[j][1]);
      *(float2*)(dst + (g + 24) * OPITCH + f) = make_float2(Od[j][2], Od[j][3]);
    }
    if (qd == 0) {
      float* lb = sL + band * 32;
      lb[g] = s0;
      lb[g + 8] = s1;
      lb[g + 16] = s2;
      lb[g + 24] = s3;
    }
  }
  __syncthreads();
  if (nh == 0) {
    const float* src = sO + band * 32 * OPITCH;
    const float* lb = sL + band * 32;
    const float r0 = 1.0f / (s0 + lb[g]);
    const float r1 = 1.0f / (s1 + lb[g + 8]);
    const float r2 = 1.0f / (s2 + lb[g + 16]);
    const float r3 = 1.0f / (s3 + lb[g + 24]);
    float* Ob = Og + ((size_t)(b * NQ + qt * 128 + band * 32)) * FF;
#pragma unroll
    for (int j = 0; j < 16; ++j) {
      int f = j * 8 + qd * 2;
      float2 a0 = *(const float2*)(src + g * OPITCH + f);
      float2 a1 = *(const float2*)(src + (g + 8) * OPITCH + f);
      float2 a2 = *(const float2*)(src + (g + 16) * OPITCH + f);
      float2 a3 = *(const float2*)(src + (g + 24) * OPITCH + f);
      *(float2*)(Ob + (size_t)g * FF + f) =
          make_float2((Ou[j][0] + a0.x) * r0, (Ou[j][1] + a0.y) * r0);
      *(float2*)(Ob + (size_t)(g + 8) * FF + f) =
          make_float2((Ou[j][2] + a1.x) * r1, (Ou[j][3] + a1.y) * r1);
      *(float2*)(Ob + (size_t)(g + 16) * FF + f) =
          make_float2((Od[j][0] + a2.x) * r2, (Od[j][1] + a2.y) * r2);
      *(float2*)(Ob + (size_t)(g + 24) * FF + f) =
          make_float2((Od[j][2] + a3.x) * r3, (Od[j][3] + a3.y) * r3);
    }
  }
}

// ===========================================================================
extern "C" void kernel_launch(void* const* d_in, const int* in_sizes, int n_in,
                              void* d_out, int out_size) {
  const float* qin  = (const float*)d_in[0];
  const float* kvin = (const float*)d_in[1];
  const float* Wq   = (const float*)d_in[2];
  const float* bq   = (const float*)d_in[3];
  const float* Wk   = (const float*)d_in[4];
  const float* bk   = (const float*)d_in[5];
  const float* Wv   = (const float*)d_in[6];
  const float* bv   = (const float*)d_in[7];
  float* out = (float*)d_out;

  __half *dQ, *dK, *dVT, *dWT;
  cudaGetSymbolAddress((void**)&dQ, g_Q);
  cudaGetSymbolAddress((void**)&dK, g_K);
  cudaGetSymbolAddress((void**)&dVT, g_VT);
  cudaGetSymbolAddress((void**)&dWT, g_WT);

  const int smq = 2 * 32768;
  const int smkv = 3 * 32768;
  const int smf = 4 * TILE_B;  // 139264 (double-buffered: best measured)
  cudaFuncSetAttribute(proj_q, cudaFuncAttributeMaxDynamicSharedMemorySize, smq);
  cudaFuncSetAttribute(proj_kv, cudaFuncAttributeMaxDynamicSharedMemorySize, smkv);
  cudaFuncSetAttribute(flash_kernel, cudaFuncAttributeMaxDynamicSharedMemorySize, smf);

  prep_wt<<<48, 256>>>(Wq, Wk, Wv, dWT);

  // Q pre-scale: log2(e)/sqrt(128); flash uses exp2
  const float qscale = 0.127518749639422f;
  proj_q<<<BB * NQ / 128, 256, smq>>>(qin, dWT, bq, dQ, qscale);
  proj_kv<<<BB * NKV / 128, 512, smkv>>>(kvin, dWT + CC * FF, dWT + 2 * CC * FF,
                                         bk, bv, dK, dVT);

  dim3 fg(NQ / 128, BB);
  flash_kernel<<<fg, 256, smf>>>(dQ, dK, dVT, out);
}

// round 16
// speedup vs baseline: 1.1097x; 1.0110x over previous
#include <cuda_runtime.h>
#include <cuda_fp16.h>
#include <cstdint>
#include <math.h>

#define BB 4
#define NQ 4096
#define NKV 4096
#define CC 128
#define FF 128
#define BN 128
#define NT (NKV / BN)
#define NKVB (BB * NKV / 128)  // 128 kv-role blocks
#define REG 16384              // projection kernels: 64-col half-region
#define TPADB 272              // flash: padded row pitch (bytes)
#define TILE_B (128 * TPADB)   // 34816 B per staged tile
#define OPITCH 132             // epilogue smem float pitch

// fp16 operands (device globals: allocation-free rule)
__device__ __half g_Q[BB * NQ * FF];    // [b,n,f] pre-scaled by log2e/sqrt(128)
__device__ __half g_K[BB * NKV * FF];   // [b,m,f]
__device__ __half g_VT[BB * FF * NKV];  // [b,f,m]
__device__ __half g_WT[3 * CC * FF];    // Wq^T, Wk^T, Wv^T fp16 [f][c]

// ---------------------------------------------------------------------------
__device__ __forceinline__ uint32_t smem_u32(const void* p) {
  uint32_t a;
  asm("{ .reg .u64 t; cvta.to.shared.u64 t, %1; cvt.u32.u64 %0, t; }" : "=r"(a) : "l"(p));
  return a;
}
__device__ __forceinline__ uint32_t swz(uint32_t r, uint32_t cb) {
  return r * 128u + (cb ^ ((r & 7u) << 4));
}
__device__ __forceinline__ float ex2f(float x) {
  float y;
  asm("ex2.approx.f32 %0, %1;" : "=f"(y) : "f"(x));
  return y;
}

#define LDSM_X4(bb, addr)                                                      \
  asm volatile("ldmatrix.sync.aligned.m8n8.x4.shared.b16 {%0,%1,%2,%3}, [%4];" \
               : "=r"((bb)[0]), "=r"((bb)[1]), "=r"((bb)[2]), "=r"((bb)[3])    \
               : "r"(addr))

__device__ __forceinline__ void mma16816(float c[4], const uint32_t a[4],
                                         const uint32_t b[2]) {
  asm volatile(
      "mma.sync.aligned.m16n8k16.row.col.f32.f16.f16.f32 "
      "{%0,%1,%2,%3}, {%4,%5,%6,%7}, {%8,%9}, {%0,%1,%2,%3};"
      : "+f"(c[0]), "+f"(c[1]), "+f"(c[2]), "+f"(c[3])
      : "r"(a[0]), "r"(a[1]), "r"(a[2]), "r"(a[3]), "r"(b[0]), "r"(b[1]));
}

#define CP_COMMIT() asm volatile("cp.async.commit_group;" ::: "memory")
#define CP_WAIT1() asm volatile("cp.async.wait_group 1;" ::: "memory")
#define CP_WAIT0() asm volatile("cp.async.wait_group 0;" ::: "memory")
#define CP16(dst, src) \
  asm volatile("cp.async.ca.shared.global [%0], [%1], 16;" ::"r"(dst), "l"(src) : "memory")

// flash staging: 128x128 fp16 tile into TPADB-padded smem (256 threads)
__device__ __forceinline__ void stage_async(const __half* __restrict__ g,
                                            size_t gstride, char* s, int t) {
  uint32_t sb = smem_u32(s);
#pragma unroll
  for (int i = 0; i < 8; ++i) {
    int idx = t + i * 256;
    int r = idx >> 4, c = idx & 15;
    uint32_t dst = sb + r * TPADB + c * 16;
    CP16(dst, (const void*)(g + (size_t)r * gstride + c * 8));
  }
}

// projection staging: 128x128 fp16 tile into 2 swizzled 16KB regions
template <int NTH>
__device__ __forceinline__ void stage_tile_swz(const __half* __restrict__ g,
                                               size_t gstride, uint32_t sb, int t) {
#pragma unroll
  for (int i = 0; i < 2048 / NTH; ++i) {
    int idx = t + i * NTH;
    uint32_t r = idx >> 4, c = idx & 15;
    uint32_t dst = sb + (c >> 3) * REG + swz(r, (c & 7) * 16);
    CP16(dst, (const void*)(g + (size_t)r * gstride + c * 8));
  }
}

// ===========================================================================
// prep: W fp32 [c][f] -> WT fp16 [f][c].  48 blocks: (matrix, f-stripe of 8).
// ===========================================================================
__global__ __launch_bounds__(256) void prep_wt(const float* __restrict__ Wq,
                                               const float* __restrict__ Wk,
                                               const float* __restrict__ Wv,
                                               __half* __restrict__ WT) {
  const int m = blockIdx.x >> 4, stripe = blockIdx.x & 15;
  const float* W = m == 0 ? Wq : (m == 1 ? Wk : Wv);
  __half* O = WT + m * (CC * FF);
  const int t = threadIdx.x;
#pragma unroll
  for (int i = 0; i < 4; ++i) {
    int idx = t + i * 256;
    int f = stripe * 8 + (idx >> 7), c = idx & 127;
    O[f * CC + c] = __float2half(W[c * FF + f]);
  }
}

// ---------------------------------------------------------------------------
template <int NTH>
__device__ __forceinline__ void stage_x_fp16(const float* __restrict__ X,
                                             char* sX, int t) {
#pragma unroll
  for (int i = 0; i < 4096 / NTH; ++i) {
    int idx = t + i * NTH;
    uint32_t r = idx >> 5, cq = idx & 31;
    float4 v = *(const float4*)(X + (size_t)r * CC + cq * 4);
    __half2 h0 = __floats2half2_rn(v.x, v.y);
    __half2 h1 = __floats2half2_rn(v.z, v.w);
    uint32_t fb = cq * 8;
    uint32_t off = (fb >> 7) * REG + swz(r, fb & 127);
    *(uint2*)(sX + off) = make_uint2(*(uint32_t*)&h0, *(uint32_t*)&h1);
  }
}

__device__ __forceinline__ void load_afrags(uint32_t Af[8][4], uint32_t base,
                                            int bd, int lane) {
  uint32_t ar = bd * 16 + (lane & 15);
#pragma unroll
  for (int k = 0; k < 8; ++k) {
    uint32_t fb = k * 32 + (lane >> 4) * 16;
    LDSM_X4(Af[k], base + (fb >> 7) * REG + swz(ar, fb & 127));
  }
}

__device__ __forceinline__ void gemm_16x64(float c[8][4], const uint32_t Af[8][4],
                                           uint32_t bbase, int nh, int lane) {
  uint32_t br = nh * 64 + (lane & 7);
  uint32_t cb8 = ((lane >> 3) & 3) * 16;
#pragma unroll
  for (int jq = 0; jq < 2; ++jq)
#pragma unroll
    for (int p = 0; p < 4; ++p)
#pragma unroll
      for (int jj = 0; jj < 4; ++jj) {
        int j = jq * 4 + jj;
        uint32_t r = br + j * 8;
        uint32_t fb = p * 64 + cb8;
        uint32_t bb[4];
        LDSM_X4(bb, bbase + (fb >> 7) * REG + swz(r, fb & 127));
        mma16816(c[j], Af[2 * p], bb);
        mma16816(c[j], Af[2 * p + 1], bb + 2);
      }
}

// ===========================================================================
// proj_all: ONE launch for all projections. 512 threads, grid = 256.
//   blocks [0, NKVB)      : kv role — K = X@Wk + bk, VT = (X@Wv + bv)^T
//   blocks [NKVB, NKVB+128): q role — Q = (X@Wq + bq) * qscale
// Both roles: warp = (band = w>>1 in 0..7, nh = w&1), one pass, 128 rows.
// ===========================================================================
__global__ __launch_bounds__(512) void proj_all(
    const float* __restrict__ Xq, const float* __restrict__ Xkv,
    const __half* __restrict__ WT,  // [WqT | WkT | WvT]
    const float* __restrict__ bq, const float* __restrict__ bk,
    const float* __restrict__ bv, __half* __restrict__ Q,
    __half* __restrict__ K, __half* __restrict__ VT, float qscale) {
  extern __shared__ char sm[];
  char* sX = sm;
  char* sW0 = sm + 32768;
  char* sW1 = sm + 65536;
  const int t = threadIdx.x, lane = t & 31, w = t >> 5;
  const int band = w >> 1, nh = w & 1, g = lane >> 2, qd = lane & 3;

  if (blockIdx.x < NKVB) {
    // ------------------------- kv role -------------------------
    const size_t R0 = (size_t)blockIdx.x * 128;
    stage_tile_swz<512>(WT + CC * FF, CC, smem_u32(sW0), t);      // WkT
    stage_tile_swz<512>(WT + 2 * CC * FF, CC, smem_u32(sW1), t);  // WvT
    CP_COMMIT();
    stage_x_fp16<512>(Xkv + R0 * CC, sX, t);
    CP_WAIT0();
    __syncthreads();

    // K projection
    {
      uint32_t Af[8][4];
      load_afrags(Af, smem_u32(sX), band, lane);
      float c[8][4];
#pragma unroll
      for (int j = 0; j < 8; ++j)
#pragma unroll
        for (int i = 0; i < 4; ++i) c[j][i] = 0.f;
      gemm_16x64(c, Af, smem_u32(sW0), nh, lane);

      const size_t r0 = R0 + band * 16 + g;
#pragma unroll
      for (int j = 0; j < 8; ++j) {
        int f = nh * 64 + j * 8 + qd * 2;
        float2 bv2 = *(const float2*)(bk + f);
        __half2 h0 = __floats2half2_rn(c[j][0] + bv2.x, c[j][1] + bv2.y);
        __half2 h1 = __floats2half2_rn(c[j][2] + bv2.x, c[j][3] + bv2.y);
        *(uint32_t*)(K + r0 * FF + f) = *(uint32_t*)&h0;
        *(uint32_t*)(K + (r0 + 8) * FF + f) = *(uint32_t*)&h1;
      }
    }

    // VT projection (batch-aware)
    const int bidx = (int)(R0 >> 12);
    const size_t mbase = (R0 & 4095);
    __half* VTb = VT + (size_t)bidx * FF * NKV;
    {
      uint32_t Af[8][4];
      load_afrags(Af, smem_u32(sW1), band, lane);
      float c[8][4];
#pragma unroll
      for (int j = 0; j < 8; ++j)
#pragma unroll
        for (int i = 0; i < 4; ++i) c[j][i] = 0.f;
      gemm_16x64(c, Af, smem_u32(sX), nh, lane);

      const int f0 = band * 16 + g;
      const float blo = bv[f0], bhi = bv[f0 + 8];
#pragma unroll
      for (int j = 0; j < 8; ++j) {
        size_t col = mbase + nh * 64 + j * 8 + qd * 2;
        __half2 h0 = __floats2half2_rn(c[j][0] + blo, c[j][1] + blo);
        __half2 h1 = __floats2half2_rn(c[j][2] + bhi, c[j][3] + bhi);
        *(uint32_t*)(VTb + (size_t)f0 * NKV + col) = *(uint32_t*)&h0;
        *(uint32_t*)(VTb + (size_t)(f0 + 8) * NKV + col) = *(uint32_t*)&h1;
      }
    }
  } else {
    // -------------------------- q role --------------------------
    const size_t R0 = (size_t)(blockIdx.x - NKVB) * 128;
    stage_tile_swz<512>(WT, CC, smem_u32(sW0), t);  // WqT
    CP_COMMIT();
    stage_x_fp16<512>(Xq + R0 * CC, sX, t);
    CP_WAIT0();
    __syncthreads();

    uint32_t Af[8][4];
    load_afrags(Af, smem_u32(sX), band, lane);
    float c[8][4];
#pragma unroll
    for (int j = 0; j < 8; ++j)
#pragma unroll
      for (int i = 0; i < 4; ++i) c[j][i] = 0.f;
    gemm_16x64(c, Af, smem_u32(sW0), nh, lane);

    const size_t r0 = R0 + band * 16 + g;
#pragma unroll
    for (int j = 0; j < 8; ++j) {
      int f = nh * 64 + j * 8 + qd * 2;
      float2 bv2 = *(const float2*)(bq + f);
      __half2 h0 = __floats2half2_rn((c[j][0] + bv2.x) * qscale,
                                     (c[j][1] + bv2.y) * qscale);
      __half2 h1 = __floats2half2_rn((c[j][2] + bv2.x) * qscale,
                                     (c[j][3] + bv2.y) * qscale);
      *(uint32_t*)(Q + r0 * FF + f) = *(uint32_t*)&h0;
      *(uint32_t*)(Q + (r0 + 8) * FF + f) = *(uint32_t*)&h1;
    }
  }
}

// ===========================================================================
// Flash attention (R15, best measured): 256 threads = 8 warps = 4 bands x
// 2 kv-halves, 32q x 64kv warp tile, double-buffered tiles, pipelined LDSM.
// ===========================================================================
__global__ __launch_bounds__(256, 1) void flash_kernel(
    const __half* __restrict__ Qg, const __half* __restrict__ Kg,
    const __half* __restrict__ VTg, float* __restrict__ Og) {
  extern __shared__ char smem[];
  char* sK[2] = {smem, smem + TILE_B};
  char* sV[2] = {smem + 2 * TILE_B, smem + 3 * TILE_B};

  const int t = threadIdx.x, lane = t & 31, w = t >> 5;
  const int band = w >> 1, nh = w & 1;
  const int g = lane >> 2, qd = lane & 3;
  const int b = blockIdx.y, qt = blockIdx.x;

  const __half* Qw = Qg + ((size_t)(b * NQ + qt * 128 + band * 32)) * FF;
  uint32_t Qfu[8][4], Qfd[8][4];
#pragma unroll
  for (int k = 0; k < 8; ++k) {
    int c0 = k * 16 + qd * 2;
    Qfu[k][0] = *(const uint32_t*)(Qw + g * FF + c0);
    Qfu[k][1] = *(const uint32_t*)(Qw + (g + 8) * FF + c0);
    Qfu[k][2] = *(const uint32_t*)(Qw + g * FF + c0 + 8);
    Qfu[k][3] = *(const uint32_t*)(Qw + (g + 8) * FF + c0 + 8);
    Qfd[k][0] = *(const uint32_t*)(Qw + (g + 16) * FF + c0);
    Qfd[k][1] = *(const uint32_t*)(Qw + (g + 24) * FF + c0);
    Qfd[k][2] = *(const uint32_t*)(Qw + (g + 16) * FF + c0 + 8);
    Qfd[k][3] = *(const uint32_t*)(Qw + (g + 24) * FF + c0 + 8);
  }

  const __half* Kb = Kg + (size_t)b * NKV * FF;
  const __half* Vb = VTg + (size_t)b * FF * NKV;

  stage_async(Kb, FF, sK[0], t);
  stage_async(Vb, NKV, sV[0], t);
  CP_COMMIT();

  float Ou[16][4], Od[16][4];
#pragma unroll
  for (int j = 0; j < 16; ++j)
#pragma unroll
    for (int i = 0; i < 4; ++i) { Ou[j][i] = 0.f; Od[j][i] = 0.f; }
  float s0 = 0.f, s1 = 0.f, s2 = 0.f, s3 = 0.f;

  const uint32_t lmoff = (uint32_t)(lane & 7) * TPADB + (uint32_t)(lane >> 3) * 16;
  const uint32_t khalf = (uint32_t)nh * 64 * TPADB;
  const uint32_t vcol = (uint32_t)nh * 128;

#pragma unroll 1
  for (int jt = 0; jt < NT; ++jt) {
    const int cur = jt & 1;
    if (jt + 1 < NT) {
      stage_async(Kb + (size_t)(jt + 1) * BN * FF, FF, sK[cur ^ 1], t);
      stage_async(Vb + (size_t)(jt + 1) * BN, NKV, sV[cur ^ 1], t);
      CP_COMMIT();
      CP_WAIT1();
    } else {
      CP_WAIT0();
    }
    __syncthreads();

    const uint32_t kbase = smem_u32(sK[cur]) + khalf + lmoff;
    const uint32_t vbase = smem_u32(sV[cur]) + lmoff + vcol;

#pragma unroll
    for (int jq = 0; jq < 2; ++jq) {
      const uint32_t ka = kbase + (uint32_t)jq * 4 * (8 * TPADB);

      float cu[4][4], cd[4][4];
#pragma unroll
      for (int jj = 0; jj < 4; ++jj)
#pragma unroll
        for (int i = 0; i < 4; ++i) { cu[jj][i] = 0.f; cd[jj][i] = 0.f; }

      uint32_t kb[2][4];
      LDSM_X4(kb[0], ka);
#pragma unroll
      for (int i = 0; i < 16; ++i) {
        if (i < 15) {
          int ni = i + 1;
          LDSM_X4(kb[(i + 1) & 1],
                  ka + (uint32_t)(ni & 3) * (8 * TPADB) + (ni >> 2) * 64);
        }
        const int p = i >> 2, jj = i & 3;
        mma16816(cu[jj], Qfu[2 * p], kb[i & 1]);
        mma16816(cu[jj], Qfu[2 * p + 1], kb[i & 1] + 2);
        mma16816(cd[jj], Qfd[2 * p], kb[i & 1]);
        mma16816(cd[jj], Qfd[2 * p + 1], kb[i & 1] + 2);
      }

      uint32_t vb[2][4];
      LDSM_X4(vb[0], vbase + jq * 64);

      uint32_t Pfu[2][4], Pfd[2][4];
#pragma unroll
      for (int jj = 0; jj < 4; ++jj) {
        int kk = jj >> 1, o = (jj & 1) * 2;
        float e0 = ex2f(cu[jj][0]), e1 = ex2f(cu[jj][1]);
        float e2 = ex2f(cu[jj][2]), e3 = ex2f(cu[jj][3]);
        s0 += e0 + e1;
        s1 += e2 + e3;
        __half2 hu01 = __floats2half2_rn(e0, e1);
        __half2 hu23 = __floats2half2_rn(e2, e3);
        Pfu[kk][o] = *(uint32_t*)&hu01;
        Pfu[kk][o + 1] = *(uint32_t*)&hu23;
        float f0 = ex2f(cd[jj][0]), f1 = ex2f(cd[jj][1]);
        float f2 = ex2f(cd[jj][2]), f3 = ex2f(cd[jj][3]);
        s2 += f0 + f1;
        s3 += f2 + f3;
        __half2 hd01 = __floats2half2_rn(f0, f1);
        __half2 hd23 = __floats2half2_rn(f2, f3);
        Pfd[kk][o] = *(uint32_t*)&hd01;
        Pfd[kk][o + 1] = *(uint32_t*)&hd23;
      }

#pragma unroll
      for (int j = 0; j < 16; ++j) {
        if (j < 15) {
          LDSM_X4(vb[(j + 1) & 1],
                  vbase + (uint32_t)(j + 1) * (8 * TPADB) + jq * 64);
        }
        mma16816(Ou[j], Pfu[0], vb[j & 1]);
        mma16816(Ou[j], Pfu[1], vb[j & 1] + 2);
        mma16816(Od[j], Pfd[0], vb[j & 1]);
        mma16816(Od[j], Pfd[1], vb[j & 1] + 2);
      }
    }
    __syncthreads();
  }

  s0 += __shfl_xor_sync(0xffffffffu, s0, 1);
  s0 += __shfl_xor_sync(0xffffffffu, s0, 2);
  s1 += __shfl_xor_sync(0xffffffffu, s1, 1);
  s1 += __shfl_xor_sync(0xffffffffu, s1, 2);
  s2 += __shfl_xor_sync(0xffffffffu, s2, 1);
  s2 += __shfl_xor_sync(0xffffffffu, s2, 2);
  s3 += __shfl_xor_sync(0xffffffffu, s3, 1);
  s3 += __shfl_xor_sync(0xffffffffu, s3, 2);

  float* sO = (float*)smem;
  float* sL = (float*)(smem + 4 * 32 * OPITCH * 4);
  if (nh == 1) {
    float* dst = sO + band * 32 * OPITCH;
#pragma unroll
    for (int j = 0; j < 16; ++j) {
      int f = j * 8 + qd * 2;
      *(float2*)(dst + g * OPITCH + f) = make_float2(Ou[j][0], Ou[j][1]);
      *(float2*)(dst + (g + 8) * OPITCH + f) = make_float2(Ou[j][2], Ou[j][3]);
      *(float2*)(dst + (g + 16) * OPITCH + f) = make_float2(Od[j][0], Od[j][1]);
      *(float2*)(dst + (g + 24) * OPITCH + f) = make_float2(Od[j][2], Od[j][3]);
    }
    if (qd == 0) {
      float* lb = sL + band * 32;
      lb[g] = s0;
      lb[g + 8] = s1;
      lb[g + 16] = s2;
      lb[g + 24] = s3;
    }
  }
  __syncthreads();
  if (nh == 0) {
    const float* src = sO + band * 32 * OPITCH;
    const float* lb = sL + band * 32;
    const float r0 = 1.0f / (s0 + lb[g]);
    const float r1 = 1.0f / (s1 + lb[g + 8]);
    const float r2 = 1.0f / (s2 + lb[g + 16]);
    const float r3 = 1.0f / (s3 + lb[g + 24]);
    float* Ob = Og + ((size_t)(b * NQ + qt * 128 + band * 32)) * FF;
#pragma unroll
    for (int j = 0; j < 16; ++j) {
      int f = j * 8 + qd * 2;
      float2 a0 = *(const float2*)(src + g * OPITCH + f);
      float2 a1 = *(const float2*)(src + (g + 8) * OPITCH + f);
      float2 a2 = *(const float2*)(src + (g + 16) * OPITCH + f);
      float2 a3 = *(const float2*)(src + (g + 24) * OPITCH + f);
      *(float2*)(Ob + (size_t)g * FF + f) =
          make_float2((Ou[j][0] + a0.x) * r0, (Ou[j][1] + a0.y) * r0);
      *(float2*)(Ob + (size_t)(g + 8) * FF + f) =
          make_float2((Ou[j][2] + a1.x) * r1, (Ou[j][3] + a1.y) * r1);
      *(float2*)(Ob + (size_t)(g + 16) * FF + f) =
          make_float2((Od[j][0] + a2.x) * r2, (Od[j][1] + a2.y) * r2);
      *(float2*)(Ob + (size_t)(g + 24) * FF + f) =
          make_float2((Od[j][2] + a3.x) * r3, (Od[j][3] + a3.y) * r3);
    }
  }
}

// ===========================================================================
extern "C" void kernel_launch(void* const* d_in, const int* in_sizes, int n_in,
                              void* d_out, int out_size) {
  const float* qin  = (const float*)d_in[0];
  const float* kvin = (const float*)d_in[1];
  const float* Wq   = (const float*)d_in[2];
  const float* bq   = (const float*)d_in[3];
  const float* Wk   = (const float*)d_in[4];
  const float* bk   = (const float*)d_in[5];
  const float* Wv   = (const float*)d_in[6];
  const float* bv   = (const float*)d_in[7];
  float* out = (float*)d_out;

  __half *dQ, *dK, *dVT, *dWT;
  cudaGetSymbolAddress((void**)&dQ, g_Q);
  cudaGetSymbolAddress((void**)&dK, g_K);
  cudaGetSymbolAddress((void**)&dVT, g_VT);
  cudaGetSymbolAddress((void**)&dWT, g_WT);

  const int smp = 3 * 32768;   // 96 KB (kv role uses all three regions)
  const int smf = 4 * TILE_B;  // 139264 (double-buffered: best measured)
  cudaFuncSetAttribute(proj_all, cudaFuncAttributeMaxDynamicSharedMemorySize, smp);
  cudaFuncSetAttribute(flash_kernel, cudaFuncAttributeMaxDynamicSharedMemorySize, smf);

  prep_wt<<<48, 256>>>(Wq, Wk, Wv, dWT);

  // Q pre-scale: log2(e)/sqrt(128); flash uses exp2
  const float qscale = 0.127518749639422f;
  proj_all<<<NKVB + BB * NQ / 128, 512, smp>>>(qin, kvin, dWT, bq, bk, bv,
                                               dQ, dK, dVT, qscale);

  dim3 fg(NQ / 128, BB);
  flash_kernel<<<fg, 256, smf>>>(dQ, dK, dVT, out);
}

// round 17
// speedup vs baseline: 1.1209x; 1.0101x over previous
#include <cuda_runtime.h>
#include <cuda_fp16.h>
#include <cstdint>
#include <math.h>

#define BB 4
#define NQ 4096
#define NKV 4096
#define CC 128
#define FF 128
#define BN 128
#define NT (NKV / BN)
#define NKVB (BB * NKV / 128)  // 128 kv-role blocks
#define REG 16384              // projection kernels: 64-col half-region
#define TPADB 272              // flash: padded row pitch (bytes)
#define TILE_B (128 * TPADB)   // 34816 B per staged tile
#define OPITCH 132             // epilogue smem float pitch

// fp16 operands (device globals: allocation-free rule)
__device__ __half g_Q[BB * NQ * FF];    // [b,n,f] pre-scaled by log2e/sqrt(128)
__device__ __half g_K[BB * NKV * FF];   // [b,m,f]
__device__ __half g_VT[BB * FF * NKV];  // [b,f,m]

// ---------------------------------------------------------------------------
__device__ __forceinline__ uint32_t smem_u32(const void* p) {
  uint32_t a;
  asm("{ .reg .u64 t; cvta.to.shared.u64 t, %1; cvt.u32.u64 %0, t; }" : "=r"(a) : "l"(p));
  return a;
}
__device__ __forceinline__ uint32_t swz(uint32_t r, uint32_t cb) {
  return r * 128u + (cb ^ ((r & 7u) << 4));
}
__device__ __forceinline__ float ex2f(float x) {
  float y;
  asm("ex2.approx.f32 %0, %1;" : "=f"(y) : "f"(x));
  return y;
}

#define LDSM_X4(bb, addr)                                                      \
  asm volatile("ldmatrix.sync.aligned.m8n8.x4.shared.b16 {%0,%1,%2,%3}, [%4];" \
               : "=r"((bb)[0]), "=r"((bb)[1]), "=r"((bb)[2]), "=r"((bb)[3])    \
               : "r"(addr))

__device__ __forceinline__ void mma16816(float c[4], const uint32_t a[4],
                                         const uint32_t b[2]) {
  asm volatile(
      "mma.sync.aligned.m16n8k16.row.col.f32.f16.f16.f32 "
      "{%0,%1,%2,%3}, {%4,%5,%6,%7}, {%8,%9}, {%0,%1,%2,%3};"
      : "+f"(c[0]), "+f"(c[1]), "+f"(c[2]), "+f"(c[3])
      : "r"(a[0]), "r"(a[1]), "r"(a[2]), "r"(a[3]), "r"(b[0]), "r"(b[1]));
}

#define CP_COMMIT() asm volatile("cp.async.commit_group;" ::: "memory")
#define CP_WAIT1() asm volatile("cp.async.wait_group 1;" ::: "memory")
#define CP_WAIT0() asm volatile("cp.async.wait_group 0;" ::: "memory")
#define CP16(dst, src) \
  asm volatile("cp.async.ca.shared.global [%0], [%1], 16;" ::"r"(dst), "l"(src) : "memory")

// flash staging: 128x128 fp16 tile into TPADB-padded smem (256 threads)
__device__ __forceinline__ void stage_async(const __half* __restrict__ g,
                                            size_t gstride, char* s, int t) {
  uint32_t sb = smem_u32(s);
#pragma unroll
  for (int i = 0; i < 8; ++i) {
    int idx = t + i * 256;
    int r = idx >> 4, c = idx & 15;
    uint32_t dst = sb + r * TPADB + c * 16;
    CP16(dst, (const void*)(g + (size_t)r * gstride + c * 8));
  }
}

// ---------------------------------------------------------------------------
// W fp32 [c][f] (128x128) -> transposed fp16 in 2 swizzled regions (smem).
// 512 threads: t -> (f = t&127, c-group = t>>7). Reads coalesced (32
// consecutive f per instruction); 16B stores conflict-free via swizzle.
// ---------------------------------------------------------------------------
__device__ __forceinline__ void stage_w_transpose(const float* __restrict__ W,
                                                  char* sW, int t) {
  const int f = t & 127, cg = t >> 7;
#pragma unroll
  for (int j = 0; j < 4; ++j) {
    int c0 = cg * 32 + j * 8;
    __half h[8];
#pragma unroll
    for (int k = 0; k < 8; ++k) h[k] = __float2half(W[(c0 + k) * FF + f]);
    uint32_t cb = (uint32_t)c0 * 2;
    uint32_t off = (cb >> 7) * REG + swz((uint32_t)f, cb & 127);
    *(uint4*)(sW + off) = *(uint4*)h;
  }
}

// 128x128 fp32 -> fp16 tile into 2 swizzled regions (direct stores)
template <int NTH>
__device__ __forceinline__ void stage_x_fp16(const float* __restrict__ X,
                                             char* sX, int t) {
#pragma unroll
  for (int i = 0; i < 4096 / NTH; ++i) {
    int idx = t + i * NTH;
    uint32_t r = idx >> 5, cq = idx & 31;
    float4 v = *(const float4*)(X + (size_t)r * CC + cq * 4);
    __half2 h0 = __floats2half2_rn(v.x, v.y);
    __half2 h1 = __floats2half2_rn(v.z, v.w);
    uint32_t fb = cq * 8;
    uint32_t off = (fb >> 7) * REG + swz(r, fb & 127);
    *(uint2*)(sX + off) = make_uint2(*(uint32_t*)&h0, *(uint32_t*)&h1);
  }
}

__device__ __forceinline__ void load_afrags(uint32_t Af[8][4], uint32_t base,
                                            int bd, int lane) {
  uint32_t ar = bd * 16 + (lane & 15);
#pragma unroll
  for (int k = 0; k < 8; ++k) {
    uint32_t fb = k * 32 + (lane >> 4) * 16;
    LDSM_X4(Af[k], base + (fb >> 7) * REG + swz(ar, fb & 127));
  }
}

__device__ __forceinline__ void gemm_16x64(float c[8][4], const uint32_t Af[8][4],
                                           uint32_t bbase, int nh, int lane) {
  uint32_t br = nh * 64 + (lane & 7);
  uint32_t cb8 = ((lane >> 3) & 3) * 16;
#pragma unroll
  for (int jq = 0; jq < 2; ++jq)
#pragma unroll
    for (int p = 0; p < 4; ++p)
#pragma unroll
      for (int jj = 0; jj < 4; ++jj) {
        int j = jq * 4 + jj;
        uint32_t r = br + j * 8;
        uint32_t fb = p * 64 + cb8;
        uint32_t bb[4];
        LDSM_X4(bb, bbase + (fb >> 7) * REG + swz(r, fb & 127));
        mma16816(c[j], Af[2 * p], bb);
        mma16816(c[j], Af[2 * p + 1], bb + 2);
      }
}

// ===========================================================================
// proj_all: ONE launch, no prep kernel. 512 threads, grid = 256.
//   blocks [0, NKVB)      : kv role — K = X@Wk + bk, VT = (X@Wv + bv)^T
//   blocks [NKVB, NKVB+128): q role — Q = (X@Wq + bq) * qscale
// Each block converts its own W slices (fp32 gmem -> fp16 swizzled smem).
// ===========================================================================
__global__ __launch_bounds__(512) void proj_all(
    const float* __restrict__ Xq, const float* __restrict__ Xkv,
    const float* __restrict__ Wq, const float* __restrict__ Wk,
    const float* __restrict__ Wv,
    const float* __restrict__ bq, const float* __restrict__ bk,
    const float* __restrict__ bv, __half* __restrict__ Q,
    __half* __restrict__ K, __half* __restrict__ VT, float qscale) {
  extern __shared__ char sm[];
  char* sX = sm;
  char* sW0 = sm + 32768;
  char* sW1 = sm + 65536;
  const int t = threadIdx.x, lane = t & 31, w = t >> 5;
  const int band = w >> 1, nh = w & 1, g = lane >> 2, qd = lane & 3;

  if (blockIdx.x < NKVB) {
    // ------------------------- kv role -------------------------
    const size_t R0 = (size_t)blockIdx.x * 128;
    stage_x_fp16<512>(Xkv + R0 * CC, sX, t);
    stage_w_transpose(Wk, sW0, t);
    stage_w_transpose(Wv, sW1, t);
    __syncthreads();

    // K projection
    {
      uint32_t Af[8][4];
      load_afrags(Af, smem_u32(sX), band, lane);
      float c[8][4];
#pragma unroll
      for (int j = 0; j < 8; ++j)
#pragma unroll
        for (int i = 0; i < 4; ++i) c[j][i] = 0.f;
      gemm_16x64(c, Af, smem_u32(sW0), nh, lane);

      const size_t r0 = R0 + band * 16 + g;
#pragma unroll
      for (int j = 0; j < 8; ++j) {
        int f = nh * 64 + j * 8 + qd * 2;
        float2 bv2 = *(const float2*)(bk + f);
        __half2 h0 = __floats2half2_rn(c[j][0] + bv2.x, c[j][1] + bv2.y);
        __half2 h1 = __floats2half2_rn(c[j][2] + bv2.x, c[j][3] + bv2.y);
        *(uint32_t*)(K + r0 * FF + f) = *(uint32_t*)&h0;
        *(uint32_t*)(K + (r0 + 8) * FF + f) = *(uint32_t*)&h1;
      }
    }

    // VT projection (batch-aware)
    const int bidx = (int)(R0 >> 12);
    const size_t mbase = (R0 & 4095);
    __half* VTb = VT + (size_t)bidx * FF * NKV;
    {
      uint32_t Af[8][4];
      load_afrags(Af, smem_u32(sW1), band, lane);
      float c[8][4];
#pragma unroll
      for (int j = 0; j < 8; ++j)
#pragma unroll
        for (int i = 0; i < 4; ++i) c[j][i] = 0.f;
      gemm_16x64(c, Af, smem_u32(sX), nh, lane);

      const int f0 = band * 16 + g;
      const float blo = bv[f0], bhi = bv[f0 + 8];
#pragma unroll
      for (int j = 0; j < 8; ++j) {
        size_t col = mbase + nh * 64 + j * 8 + qd * 2;
        __half2 h0 = __floats2half2_rn(c[j][0] + blo, c[j][1] + blo);
        __half2 h1 = __floats2half2_rn(c[j][2] + bhi, c[j][3] + bhi);
        *(uint32_t*)(VTb + (size_t)f0 * NKV + col) = *(uint32_t*)&h0;
        *(uint32_t*)(VTb + (size_t)(f0 + 8) * NKV + col) = *(uint32_t*)&h1;
      }
    }
  } else {
    // -------------------------- q role --------------------------
    const size_t R0 = (size_t)(blockIdx.x - NKVB) * 128;
    stage_x_fp16<512>(Xq + R0 * CC, sX, t);
    stage_w_transpose(Wq, sW0, t);
    __syncthreads();

    uint32_t Af[8][4];
    load_afrags(Af, smem_u32(sX), band, lane);
    float c[8][4];
#pragma unroll
    for (int j = 0; j < 8; ++j)
#pragma unroll
      for (int i = 0; i < 4; ++i) c[j][i] = 0.f;
    gemm_16x64(c, Af, smem_u32(sW0), nh, lane);

    const size_t r0 = R0 + band * 16 + g;
#pragma unroll
    for (int j = 0; j < 8; ++j) {
      int f = nh * 64 + j * 8 + qd * 2;
      float2 bv2 = *(const float2*)(bq + f);
      __half2 h0 = __floats2half2_rn((c[j][0] + bv2.x) * qscale,
                                     (c[j][1] + bv2.y) * qscale);
      __half2 h1 = __floats2half2_rn((c[j][2] + bv2.x) * qscale,
                                     (c[j][3] + bv2.y) * qscale);
      *(uint32_t*)(Q + r0 * FF + f) = *(uint32_t*)&h0;
      *(uint32_t*)(Q + (r0 + 8) * FF + f) = *(uint32_t*)&h1;
    }
  }
}

// ===========================================================================
// Flash attention (R15, best measured): 256 threads = 8 warps = 4 bands x
// 2 kv-halves, 32q x 64kv warp tile, double-buffered tiles, pipelined LDSM.
// ===========================================================================
__global__ __launch_bounds__(256, 1) void flash_kernel(
    const __half* __restrict__ Qg, const __half* __restrict__ Kg,
    const __half* __restrict__ VTg, float* __restrict__ Og) {
  extern __shared__ char smem[];
  char* sK[2] = {smem, smem + TILE_B};
  char* sV[2] = {smem + 2 * TILE_B, smem + 3 * TILE_B};

  const int t = threadIdx.x, lane = t & 31, w = t >> 5;
  const int band = w >> 1, nh = w & 1;
  const int g = lane >> 2, qd = lane & 3;
  const int b = blockIdx.y, qt = blockIdx.x;

  const __half* Qw = Qg + ((size_t)(b * NQ + qt * 128 + band * 32)) * FF;
  uint32_t Qfu[8][4], Qfd[8][4];
#pragma unroll
  for (int k = 0; k < 8; ++k) {
    int c0 = k * 16 + qd * 2;
    Qfu[k][0] = *(const uint32_t*)(Qw + g * FF + c0);
    Qfu[k][1] = *(const uint32_t*)(Qw + (g + 8) * FF + c0);
    Qfu[k][2] = *(const uint32_t*)(Qw + g * FF + c0 + 8);
    Qfu[k][3] = *(const uint32_t*)(Qw + (g + 8) * FF + c0 + 8);
    Qfd[k][0] = *(const uint32_t*)(Qw + (g + 16) * FF + c0);
    Qfd[k][1] = *(const uint32_t*)(Qw + (g + 24) * FF + c0);
    Qfd[k][2] = *(const uint32_t*)(Qw + (g + 16) * FF + c0 + 8);
    Qfd[k][3] = *(const uint32_t*)(Qw + (g + 24) * FF + c0 + 8);
  }

  const __half* Kb = Kg + (size_t)b * NKV * FF;
  const __half* Vb = VTg + (size_t)b * FF * NKV;

  stage_async(Kb, FF, sK[0], t);
  stage_async(Vb, NKV, sV[0], t);
  CP_COMMIT();

  float Ou[16][4], Od[16][4];
#pragma unroll
  for (int j = 0; j < 16; ++j)
#pragma unroll
    for (int i = 0; i < 4; ++i) { Ou[j][i] = 0.f; Od[j][i] = 0.f; }
  float s0 = 0.f, s1 = 0.f, s2 = 0.f, s3 = 0.f;

  const uint32_t lmoff = (uint32_t)(lane & 7) * TPADB + (uint32_t)(lane >> 3) * 16;
  const uint32_t khalf = (uint32_t)nh * 64 * TPADB;
  const uint32_t vcol = (uint32_t)nh * 128;

#pragma unroll 1
  for (int jt = 0; jt < NT; ++jt) {
    const int cur = jt & 1;
    if (jt + 1 < NT) {
      stage_async(Kb + (size_t)(jt + 1) * BN * FF, FF, sK[cur ^ 1], t);
      stage_async(Vb + (size_t)(jt + 1) * BN, NKV, sV[cur ^ 1], t);
      CP_COMMIT();
      CP_WAIT1();
    } else {
      CP_WAIT0();
    }
    __syncthreads();

    const uint32_t kbase = smem_u32(sK[cur]) + khalf + lmoff;
    const uint32_t vbase = smem_u32(sV[cur]) + lmoff + vcol;

#pragma unroll
    for (int jq = 0; jq < 2; ++jq) {
      const uint32_t ka = kbase + (uint32_t)jq * 4 * (8 * TPADB);

      float cu[4][4], cd[4][4];
#pragma unroll
      for (int jj = 0; jj < 4; ++jj)
#pragma unroll
        for (int i = 0; i < 4; ++i) { cu[jj][i] = 0.f; cd[jj][i] = 0.f; }

      uint32_t kb[2][4];
      LDSM_X4(kb[0], ka);
#pragma unroll
      for (int i = 0; i < 16; ++i) {
        if (i < 15) {
          int ni = i + 1;
          LDSM_X4(kb[(i + 1) & 1],
                  ka + (uint32_t)(ni & 3) * (8 * TPADB) + (ni >> 2) * 64);
        }
        const int p = i >> 2, jj = i & 3;
        mma16816(cu[jj], Qfu[2 * p], kb[i & 1]);
        mma16816(cu[jj], Qfu[2 * p + 1], kb[i & 1] + 2);
        mma16816(cd[jj], Qfd[2 * p], kb[i & 1]);
        mma16816(cd[jj], Qfd[2 * p + 1], kb[i & 1] + 2);
      }

      uint32_t vb[2][4];
      LDSM_X4(vb[0], vbase + jq * 64);

      uint32_t Pfu[2][4], Pfd[2][4];
#pragma unroll
      for (int jj = 0; jj < 4; ++jj) {
        int kk = jj >> 1, o = (jj & 1) * 2;
        float e0 = ex2f(cu[jj][0]), e1 = ex2f(cu[jj][1]);
        float e2 = ex2f(cu[jj][2]), e3 = ex2f(cu[jj][3]);
        s0 += e0 + e1;
        s1 += e2 + e3;
        __half2 hu01 = __floats2half2_rn(e0, e1);
        __half2 hu23 = __floats2half2_rn(e2, e3);
        Pfu[kk][o] = *(uint32_t*)&hu01;
        Pfu[kk][o + 1] = *(uint32_t*)&hu23;
        float f0 = ex2f(cd[jj][0]), f1 = ex2f(cd[jj][1]);
        float f2 = ex2f(cd[jj][2]), f3 = ex2f(cd[jj][3]);
        s2 += f0 + f1;
        s3 += f2 + f3;
        __half2 hd01 = __floats2half2_rn(f0, f1);
        __half2 hd23 = __floats2half2_rn(f2, f3);
        Pfd[kk][o] = *(uint32_t*)&hd01;
        Pfd[kk][o + 1] = *(uint32_t*)&hd23;
      }

#pragma unroll
      for (int j = 0; j < 16; ++j) {
        if (j < 15) {
          LDSM_X4(vb[(j + 1) & 1],
                  vbase + (uint32_t)(j + 1) * (8 * TPADB) + jq * 64);
        }
        mma16816(Ou[j], Pfu[0], vb[j & 1]);
        mma16816(Ou[j], Pfu[1], vb[j & 1] + 2);
        mma16816(Od[j], Pfd[0], vb[j & 1]);
        mma16816(Od[j], Pfd[1], vb[j & 1] + 2);
      }
    }
    __syncthreads();
  }

  s0 += __shfl_xor_sync(0xffffffffu, s0, 1);
  s0 += __shfl_xor_sync(0xffffffffu, s0, 2);
  s1 += __shfl_xor_sync(0xffffffffu, s1, 1);
  s1 += __shfl_xor_sync(0xffffffffu, s1, 2);
  s2 += __shfl_xor_sync(0xffffffffu, s2, 1);
  s2 += __shfl_xor_sync(0xffffffffu, s2, 2);
  s3 += __shfl_xor_sync(0xffffffffu, s3, 1);
  s3 += __shfl_xor_sync(0xffffffffu, s3, 2);

  float* sO = (float*)smem;
  float* sL = (float*)(smem + 4 * 32 * OPITCH * 4);
  if (nh == 1) {
    float* dst = sO + band * 32 * OPITCH;
#pragma unroll
    for (int j = 0; j < 16; ++j) {
      int f = j * 8 + qd * 2;
      *(float2*)(dst + g * OPITCH + f) = make_float2(Ou[j][0], Ou[j][1]);
      *(float2*)(dst + (g + 8) * OPITCH + f) = make_float2(Ou[j][2], Ou[j][3]);
      *(float2*)(dst + (g + 16) * OPITCH + f) = make_float2(Od[j][0], Od[j][1]);
      *(float2*)(dst + (g + 24) * OPITCH + f) = make_float2(Od[j][2], Od[j][3]);
    }
    if (qd == 0) {
      float* lb = sL + band * 32;
      lb[g] = s0;
      lb[g + 8] = s1;
      lb[g + 16] = s2;
      lb[g + 24] = s3;
    }
  }
  __syncthreads();
  if (nh == 0) {
    const float* src = sO + band * 32 * OPITCH;
    const float* lb = sL + band * 32;
    const float r0 = 1.0f / (s0 + lb[g]);
    const float r1 = 1.0f / (s1 + lb[g + 8]);
    const float r2 = 1.0f / (s2 + lb[g + 16]);
    const float r3 = 1.0f / (s3 + lb[g + 24]);
    float* Ob = Og + ((size_t)(b * NQ + qt * 128 + band * 32)) * FF;
#pragma unroll
    for (int j = 0; j < 16; ++j) {
      int f = j * 8 + qd * 2;
      float2 a0 = *(const float2*)(src + g * OPITCH + f);
      float2 a1 = *(const float2*)(src + (g + 8) * OPITCH + f);
      float2 a2 = *(const float2*)(src + (g + 16) * OPITCH + f);
      float2 a3 = *(const float2*)(src + (g + 24) * OPITCH + f);
      *(float2*)(Ob + (size_t)g * FF + f) =
          make_float2((Ou[j][0] + a0.x) * r0, (Ou[j][1] + a0.y) * r0);
      *(float2*)(Ob + (size_t)(g + 8) * FF + f) =
          make_float2((Ou[j][2] + a1.x) * r1, (Ou[j][3] + a1.y) * r1);
      *(float2*)(Ob + (size_t)(g + 16) * FF + f) =
          make_float2((Od[j][0] + a2.x) * r2, (Od[j][1] + a2.y) * r2);
      *(float2*)(Ob + (size_t)(g + 24) * FF + f) =
          make_float2((Od[j][2] + a3.x) * r3, (Od[j][3] + a3.y) * r3);
    }
  }
}

// ===========================================================================
extern "C" void kernel_launch(void* const* d_in, const int* in_sizes, int n_in,
                              void* d_out, int out_size) {
  const float* qin  = (const float*)d_in[0];
  const float* kvin = (const float*)d_in[1];
  const float* Wq   = (const float*)d_in[2];
  const float* bq   = (const float*)d_in[3];
  const float* Wk   = (const float*)d_in[4];
  const float* bk   = (const float*)d_in[5];
  const float* Wv   = (const float*)d_in[6];
  const float* bv   = (const float*)d_in[7];
  float* out = (float*)d_out;

  __half *dQ, *dK, *dVT;
  cudaGetSymbolAddress((void**)&dQ, g_Q);
  cudaGetSymbolAddress((void**)&dK, g_K);
  cudaGetSymbolAddress((void**)&dVT, g_VT);

  const int smp = 3 * 32768;   // 96 KB (kv role uses all three regions)
  const int smf = 4 * TILE_B;  // 139264 (double-buffered: best measured)
  cudaFuncSetAttribute(proj_all, cudaFuncAttributeMaxDynamicSharedMemorySize, smp);
  cudaFuncSetAttribute(flash_kernel, cudaFuncAttributeMaxDynamicSharedMemorySize, smf);

  // Q pre-scale: log2(e)/sqrt(128); flash uses exp2
  const float qscale = 0.127518749639422f;
  proj_all<<<NKVB + BB * NQ / 128, 512, smp>>>(qin, kvin, Wq, Wk, Wv,
                                               bq, bk, bv, dQ, dK, dVT, qscale);

  dim3 fg(NQ / 128, BB);
  flash_kernel<<<fg, 256, smf>>>(dQ, dK, dVT, out);
}